// round 3
// baseline (speedup 1.0000x reference)
#include <cuda_runtime.h>
#include <cstdint>
#include <cstddef>

#define S_LEN 128
#define BATCH 32
#define NIN   512
#define HID   512
#define NLAYER 3
#define VSZ   1536
#define NVOC  50257
#define MROWS (S_LEN*BATCH)
#define LSTM_NCTA 96

__device__ float g_x [MROWS*NIN];
__device__ float g_Hc[(S_LEN+1)*BATCH*VSZ];
__device__ float g_y [MROWS*HID];
__device__ unsigned g_arrive;
__device__ unsigned g_epoch;

__device__ __forceinline__ unsigned f2tf(float f) {
    unsigned r; asm("cvt.rna.tf32.f32 %0, %1;" : "=r"(r) : "f"(f)); return r;
}
__device__ __forceinline__ void mma8(float* c, unsigned a0, unsigned a1,
                                     unsigned a2, unsigned a3,
                                     unsigned b0, unsigned b1) {
    asm volatile(
        "mma.sync.aligned.m16n8k8.row.col.f32.tf32.tf32.f32 "
        "{%0,%1,%2,%3}, {%4,%5,%6,%7}, {%8,%9}, {%0,%1,%2,%3};"
        : "+f"(c[0]), "+f"(c[1]), "+f"(c[2]), "+f"(c[3])
        : "r"(a0), "r"(a1), "r"(a2), "r"(a3), "r"(b0), "r"(b1));
}
__device__ __forceinline__ float sigm(float x) { return 1.f / (1.f + expf(-x)); }

// ---------------- embed gather + state init ----------------
__global__ void __launch_bounds__(256) init_embed(const int* __restrict__ ids,
                                                  const float* __restrict__ emb) {
    int blk = blockIdx.x;
    if (blk < MROWS) {
        int id = ids[blk];
        const float* src = emb + (size_t)id * NIN;
        float* dst = g_x + (size_t)blk * NIN;
        for (int k = threadIdx.x; k < NIN; k += 256) dst[k] = src[k];
    } else {
        int z = blk - MROWS;  // 0..15 zero g_Hc slot 0 (49152 floats)
        for (int i = threadIdx.x; i < 3072; i += 256) g_Hc[(size_t)z*3072 + i] = 0.f;
        if (z == 0 && threadIdx.x == 0) { g_arrive = 0u; g_epoch = 0u; }
    }
}

// ---------------- persistent wavefront LSTM ----------------
__global__ void __launch_bounds__(256) lstm_wave(
    const float* __restrict__ Wi, const float* __restrict__ bi,
    const float* __restrict__ Wf, const float* __restrict__ bf,
    const float* __restrict__ Wo, const float* __restrict__ bo,
    const float* __restrict__ Wg, const float* __restrict__ bg,
    const float* __restrict__ pci, const float* __restrict__ pcf,
    const float* __restrict__ pco)
{
    __shared__ float As[32][68];
    __shared__ float Bs[64][68];
    __shared__ float Cs[32][64];
    __shared__ float c_state[32][16];
    __shared__ float sbi[16], sbf[16], sbo[16], sbg[16], spi[16], spf[16], spo[16];

    const int cta = blockIdx.x;
    const int j   = cta >> 5;
    const int n0  = (cta & 31) * 16;
    const int tid = threadIdx.x;
    const int warp = tid >> 5, lane = tid & 31;
    const int g = lane >> 2, tq = lane & 3;
    const int wm = warp & 1;
    const int wn = warp >> 1;

    if (tid < 16) {
        int idx = j * HID + n0 + tid;
        sbi[tid] = bi[idx];  sbf[tid] = bf[idx];  sbo[tid] = bo[idx];  sbg[tid] = bg[idx];
        spi[tid] = pci[idx]; spf[tid] = pcf[idx]; spo[tid] = pco[idx];
    }
    for (int i = tid; i < 32*16; i += 256) ((float*)c_state)[i] = 0.f;
    __syncthreads();

    const int Keff = (j == 0) ? 1024 : 1536;
    const int nk = Keff >> 6;   // BK = 64

    for (int w = 0; w < S_LEN + NLAYER - 1; ++w) {
        const int t = w - j;
        if (t >= 0 && t < S_LEN) {
            float acc[2][4] = {};
            float4 ra[2], rb[4];

            auto loadA = [&](int kk) {
#pragma unroll
                for (int q = 0; q < 2; ++q) {
                    int p = tid + q*256, row = p >> 4, c4 = p & 15;
                    int kc = kk + c4*4;
                    int kr = (j == 0 && kc >= 512) ? kc + 512 : kc;
                    const float* src;
                    if (kr < 512)
                        src = g_x + (size_t)(t*BATCH + row)*NIN + kr;
                    else if (kr < 1024)
                        src = g_Hc + (size_t)((t+1)*BATCH + row)*VSZ + (j-1)*HID + (kr-512);
                    else
                        src = g_Hc + (size_t)(t*BATCH + row)*VSZ + j*HID + (kr-1024);
                    ra[q] = *(const float4*)src;
                }
            };
            auto loadB = [&](int kk) {
#pragma unroll
                for (int q = 0; q < 4; ++q) {
                    int p = tid + q*256, row = p >> 4, c4 = p & 15;
                    int gate = row >> 4;
                    int n = n0 + (row & 15);
                    int kc = kk + c4*4;
                    int kr = (j == 0 && kc >= 512) ? kc + 512 : kc;
                    const float* wp = (gate == 0) ? Wi : (gate == 1) ? Wf : (gate == 2) ? Wo : Wg;
                    rb[q] = *(const float4*)(wp + (size_t)(j*HID + n)*VSZ + kr);
                }
            };

            loadA(0); loadB(0);
            for (int kt = 0; kt < nk; ++kt) {
                __syncthreads();
#pragma unroll
                for (int q = 0; q < 2; ++q) {
                    int p = tid + q*256, row = p >> 4, c4 = p & 15;
                    float* d = &As[row][c4*4];
                    d[0] = __uint_as_float(f2tf(ra[q].x));
                    d[1] = __uint_as_float(f2tf(ra[q].y));
                    d[2] = __uint_as_float(f2tf(ra[q].z));
                    d[3] = __uint_as_float(f2tf(ra[q].w));
                }
#pragma unroll
                for (int q = 0; q < 4; ++q) {
                    int p = tid + q*256, row = p >> 4, c4 = p & 15;
                    float* d = &Bs[row][c4*4];
                    d[0] = __uint_as_float(f2tf(rb[q].x));
                    d[1] = __uint_as_float(f2tf(rb[q].y));
                    d[2] = __uint_as_float(f2tf(rb[q].z));
                    d[3] = __uint_as_float(f2tf(rb[q].w));
                }
                __syncthreads();
                if (kt + 1 < nk) { loadA((kt+1)*64); loadB((kt+1)*64); }
#pragma unroll
                for (int k8 = 0; k8 < 8; ++k8) {
                    int kc = k8*8 + tq;
                    unsigned a0 = __float_as_uint(As[wm*16 + g][kc]);
                    unsigned a1 = __float_as_uint(As[wm*16 + g + 8][kc]);
                    unsigned a2 = __float_as_uint(As[wm*16 + g][kc + 4]);
                    unsigned a3 = __float_as_uint(As[wm*16 + g + 8][kc + 4]);
#pragma unroll
                    for (int nt = 0; nt < 2; ++nt) {
                        unsigned b0 = __float_as_uint(Bs[wn*16 + nt*8 + g][kc]);
                        unsigned b1 = __float_as_uint(Bs[wn*16 + nt*8 + g][kc + 4]);
                        mma8(acc[nt], a0, a1, a2, a3, b0, b1);
                    }
                }
            }
#pragma unroll
            for (int nt = 0; nt < 2; ++nt) {
                int col = wn*16 + nt*8 + 2*tq;
                Cs[wm*16 + g][col]         = acc[nt][0];
                Cs[wm*16 + g][col + 1]     = acc[nt][1];
                Cs[wm*16 + g + 8][col]     = acc[nt][2];
                Cs[wm*16 + g + 8][col + 1] = acc[nt][3];
            }
            __syncthreads();
            for (int p = tid; p < 512; p += 256) {
                int b = p >> 4, hc = p & 15;
                float zi = Cs[b][hc],      zf = Cs[b][16 + hc];
                float zo = Cs[b][32 + hc], zg = Cs[b][48 + hc];
                float c = c_state[b][hc];
                float it = sigm(zi + sbi[hc] + spi[hc]*c);
                float ft = sigm(zf + sbf[hc] + spf[hc]*c);
                float ct = it * tanhf(zg + sbg[hc]) + ft * c;
                float ot = sigm(zo + sbo[hc] + spo[hc]*c);   // peephole on OLD c
                float h  = ot * tanhf(ct);
                c_state[b][hc] = ct;
                g_Hc[(size_t)((t+1)*BATCH + b)*VSZ + j*HID + n0 + hc] = h;
            }
        }
        // grid barrier
        __threadfence();
        __syncthreads();
        if (tid == 0) {
            unsigned arr = atomicAdd(&g_arrive, 1u) + 1u;
            if (arr == (unsigned)((w + 1) * LSTM_NCTA)) {
                atomicExch(&g_epoch, (unsigned)(w + 1));
            } else {
                volatile unsigned* ep = &g_epoch;
                while (*ep < (unsigned)(w + 1)) {}
                __threadfence();
            }
        }
        __syncthreads();
    }
}

// ---------------- C[M,N] = A[M,K] @ W[N,K]^T + bias ----------------
// BM=128, BN=128, BK=16, 256 threads (8 warps: 4 M x 2 N). M % 128 == 0.
__global__ void __launch_bounds__(256) gemm_bias(
    const float* __restrict__ A, int lda,
    const float* __restrict__ W, const float* __restrict__ bias,
    float* __restrict__ C, int N, int K)
{
    __shared__ float As[128][20];
    __shared__ float Bs[128][20];

    const int m0 = blockIdx.x * 128;
    const int n0 = blockIdx.y * 128;
    const int tid = threadIdx.x;
    const int warp = tid >> 5, lane = tid & 31;
    const int g = lane >> 2, tq = lane & 3;
    const int wm = warp & 3, wn = warp >> 2;
    const int row = tid >> 2, c4 = tid & 3;

    float acc[2][8][4] = {};
    float4 ra[2], rb[2];

    auto loadG = [&](int kk) {
#pragma unroll
        for (int q = 0; q < 2; ++q) {
            int r = row + q*64;
            ra[q] = *(const float4*)(A + (size_t)(m0 + r)*lda + kk + c4*4);
            int n = n0 + r;
            if (n < N) rb[q] = *(const float4*)(W + (size_t)n*K + kk + c4*4);
            else       rb[q] = make_float4(0.f, 0.f, 0.f, 0.f);
        }
    };

    const int nk = K >> 4;
    loadG(0);
    for (int kt = 0; kt < nk; ++kt) {
        __syncthreads();
#pragma unroll
        for (int q = 0; q < 2; ++q) {
            int r = row + q*64;
            float* da = &As[r][c4*4];
            da[0] = __uint_as_float(f2tf(ra[q].x));
            da[1] = __uint_as_float(f2tf(ra[q].y));
            da[2] = __uint_as_float(f2tf(ra[q].z));
            da[3] = __uint_as_float(f2tf(ra[q].w));
            float* db = &Bs[r][c4*4];
            db[0] = __uint_as_float(f2tf(rb[q].x));
            db[1] = __uint_as_float(f2tf(rb[q].y));
            db[2] = __uint_as_float(f2tf(rb[q].z));
            db[3] = __uint_as_float(f2tf(rb[q].w));
        }
        __syncthreads();
        if (kt + 1 < nk) loadG((kt+1)*16);
#pragma unroll
        for (int k8 = 0; k8 < 2; ++k8) {
            int kc = k8*8 + tq;
            unsigned a[2][4];
#pragma unroll
            for (int mf = 0; mf < 2; ++mf) {
                int r = wm*32 + mf*16 + g;
                a[mf][0] = __float_as_uint(As[r][kc]);
                a[mf][1] = __float_as_uint(As[r + 8][kc]);
                a[mf][2] = __float_as_uint(As[r][kc + 4]);
                a[mf][3] = __float_as_uint(As[r + 8][kc + 4]);
            }
#pragma unroll
            for (int nf = 0; nf < 8; ++nf) {
                unsigned b0 = __float_as_uint(Bs[wn*64 + nf*8 + g][kc]);
                unsigned b1 = __float_as_uint(Bs[wn*64 + nf*8 + g][kc + 4]);
#pragma unroll
                for (int mf = 0; mf < 2; ++mf)
                    mma8(acc[mf][nf], a[mf][0], a[mf][1], a[mf][2], a[mf][3], b0, b1);
            }
        }
    }
#pragma unroll
    for (int mf = 0; mf < 2; ++mf) {
#pragma unroll
        for (int nf = 0; nf < 8; ++nf) {
            int r  = m0 + wm*32 + mf*16 + g;
            int cn = n0 + wn*64 + nf*8 + 2*tq;
            if (cn < N)     C[(size_t)r*N + cn]           = acc[mf][nf][0] + bias[cn];
            if (cn + 1 < N) C[(size_t)r*N + cn + 1]       = acc[mf][nf][1] + bias[cn+1];
            if (cn < N)     C[(size_t)(r+8)*N + cn]       = acc[mf][nf][2] + bias[cn];
            if (cn + 1 < N) C[(size_t)(r+8)*N + cn + 1]   = acc[mf][nf][3] + bias[cn+1];
        }
    }
}

extern "C" void kernel_launch(void* const* d_in, const int* in_sizes, int n_in,
                              void* d_out, int out_size) {
    const int*   ids  = (const int*)  d_in[0];
    const float* emb  = (const float*)d_in[1];
    const float* Wi   = (const float*)d_in[2];
    const float* bi   = (const float*)d_in[3];
    const float* Wf   = (const float*)d_in[4];
    const float* bf   = (const float*)d_in[5];
    const float* Wo   = (const float*)d_in[6];
    const float* bo   = (const float*)d_in[7];
    const float* Wg   = (const float*)d_in[8];
    const float* bg   = (const float*)d_in[9];
    const float* pci  = (const float*)d_in[10];
    const float* pcf  = (const float*)d_in[11];
    const float* pco  = (const float*)d_in[12];
    const float* Why  = (const float*)d_in[13];
    const float* bhy  = (const float*)d_in[14];
    const float* Wdec = (const float*)d_in[15];
    const float* bdec = (const float*)d_in[16];
    float* out = (float*)d_out;

    float* hc_base;  float* y_base;
    cudaGetSymbolAddress((void**)&hc_base, g_Hc);
    cudaGetSymbolAddress((void**)&y_base,  g_y);

    init_embed<<<MROWS + 16, 256>>>(ids, emb);
    lstm_wave<<<LSTM_NCTA, 256>>>(Wi, bi, Wf, bf, Wo, bo, Wg, bg, pci, pcf, pco);
    // y = Hcat @ Why^T + bhy   (M=4096, N=512, K=1536); Hcat rows = g_Hc slots 1..128
    {
        dim3 grid(MROWS/128, (HID + 127)/128);
        gemm_bias<<<grid, 256>>>(hc_base + (size_t)BATCH*VSZ, VSZ, Why, bhy,
                                 y_base, HID, VSZ);
    }
    // logits = y @ Wdec^T + bdec  (M=4096, N=50257, K=512)
    {
        dim3 grid(MROWS/128, (NVOC + 127)/128);
        gemm_bias<<<grid, 256>>>(y_base, HID, Wdec, bdec, out, NVOC, HID);
    }
}

// round 4
// speedup vs baseline: 1.1412x; 1.1412x over previous
#include <cuda_runtime.h>
#include <cstdint>
#include <cstddef>

#define S_LEN 128
#define BATCH 32
#define NIN   512
#define HID   512
#define NLAYER 3
#define VSZ   1536
#define NVOC  50257
#define MROWS (S_LEN*BATCH)
#define LSTM_NCTA 96

// -------- scratch (device globals) --------
__device__ float g_x [MROWS*NIN];
__device__ float g_Hc[(S_LEN+1)*BATCH*VSZ];
__device__ float g_y [MROWS*HID];
__device__ float g_Wt[4*NLAYER*HID*VSZ];    // tf32-rounded gate weights [gate][j*H+n][VSZ]
__device__ float g_WhyT[HID*VSZ];           // tf32-rounded Why
__device__ float g_WdecT[(size_t)NVOC*HID]; // tf32-rounded Wdec
__device__ unsigned g_arrive;
__device__ unsigned g_epoch;

__device__ __forceinline__ unsigned f2tf(float f) {
    unsigned r; asm("cvt.rna.tf32.f32 %0, %1;" : "=r"(r) : "f"(f)); return r;
}
__device__ __forceinline__ float f2tff(float f) { return __uint_as_float(f2tf(f)); }
__device__ __forceinline__ void mma8(float* c, unsigned a0, unsigned a1,
                                     unsigned a2, unsigned a3,
                                     unsigned b0, unsigned b1) {
    asm volatile(
        "mma.sync.aligned.m16n8k8.row.col.f32.tf32.tf32.f32 "
        "{%0,%1,%2,%3}, {%4,%5,%6,%7}, {%8,%9}, {%0,%1,%2,%3};"
        : "+f"(c[0]), "+f"(c[1]), "+f"(c[2]), "+f"(c[3])
        : "r"(a0), "r"(a1), "r"(a2), "r"(a3), "r"(b0), "r"(b1));
}
__device__ __forceinline__ float sigm(float x) { return 1.f / (1.f + expf(-x)); }
__device__ __forceinline__ unsigned scvt(const void* p) {
    return (unsigned)__cvta_generic_to_shared(p);
}
__device__ __forceinline__ void cpa16(unsigned d, const float* s, int sz) {
    asm volatile("cp.async.cg.shared.global [%0], [%1], 16, %2;"
                 :: "r"(d), "l"(s), "r"(sz));
}
__device__ __forceinline__ void cpa_commit() { asm volatile("cp.async.commit_group;"); }

// -------- tf32 pre-round of a weight array --------
__global__ void __launch_bounds__(256) cvt_tf32(const float4* __restrict__ src,
                                                float4* __restrict__ dst, int n4) {
    for (int i = blockIdx.x*256 + threadIdx.x; i < n4; i += gridDim.x*256) {
        float4 v = src[i];
        v.x = f2tff(v.x); v.y = f2tff(v.y); v.z = f2tff(v.z); v.w = f2tff(v.w);
        dst[i] = v;
    }
}

// -------- embed gather (pre-rounded) + state init --------
__global__ void __launch_bounds__(256) init_embed(const int* __restrict__ ids,
                                                  const float* __restrict__ emb) {
    int blk = blockIdx.x;
    if (blk < MROWS) {
        int id = ids[blk];
        const float* src = emb + (size_t)id * NIN;
        float* dst = g_x + (size_t)blk * NIN;
        for (int k = threadIdx.x; k < NIN; k += 256) dst[k] = f2tff(src[k]);
    } else {
        int z = blk - MROWS;  // 0..15 zero g_Hc slot 0
        for (int i = threadIdx.x; i < 3072; i += 256) g_Hc[(size_t)z*3072 + i] = 0.f;
        if (z == 0 && threadIdx.x == 0) { g_arrive = 0u; g_epoch = 0u; }
    }
}

// -------- persistent wavefront LSTM (double-buffered, 1 sync/k-tile) --------
// smem floats: As0[2176] As1[2176] Bs0[4352] Bs1[4352] Cs[2048] cst[512] par[112]
#define L_AS(b)  (smL + (b)*2176)
#define L_BS(b)  (smL + 4352 + (b)*4352)
#define L_CS     (smL + 13056)
#define L_CST    (smL + 15104)
#define L_PAR    (smL + 15616)
#define LSTM_SMEM (15728*4)

__global__ void __launch_bounds__(256) lstm_wave(
    const float* __restrict__ bi, const float* __restrict__ bf,
    const float* __restrict__ bo, const float* __restrict__ bg,
    const float* __restrict__ pci, const float* __restrict__ pcf,
    const float* __restrict__ pco)
{
    extern __shared__ float smL[];
    const int cta = blockIdx.x;
    const int j   = cta >> 5;
    const int n0  = (cta & 31) * 16;
    const int tid = threadIdx.x;
    const int warp = tid >> 5, lane = tid & 31;
    const int g = lane >> 2, tq = lane & 3;
    const int wm = warp & 1;
    const int wn = warp >> 1;

    if (tid < 16) {
        int idx = j * HID + n0 + tid;
        L_PAR[tid]      = bi[idx];  L_PAR[16+tid] = bf[idx];
        L_PAR[32+tid]   = bo[idx];  L_PAR[48+tid] = bg[idx];
        L_PAR[64+tid]   = pci[idx]; L_PAR[80+tid] = pcf[idx];
        L_PAR[96+tid]   = pco[idx];
    }
    for (int i = tid; i < 512; i += 256) L_CST[i] = 0.f;
    __syncthreads();

    const int Keff = (j == 0) ? 1024 : 1536;
    const int nk = Keff >> 6;   // BK = 64

    for (int w = 0; w < S_LEN + NLAYER - 1; ++w) {
        const int t = w - j;
        if (t >= 0 && t < S_LEN) {
            float acc[2][4] = {};
            float4 ra[2], rb[4];

            auto loadA = [&](int kk) {
#pragma unroll
                for (int q = 0; q < 2; ++q) {
                    int p = tid + q*256, row = p >> 4, c4 = p & 15;
                    int kc = kk + c4*4;
                    int kr = (j == 0 && kc >= 512) ? kc + 512 : kc;
                    const float* src;
                    if (kr < 512)
                        src = g_x + (size_t)(t*BATCH + row)*NIN + kr;
                    else if (kr < 1024)
                        src = g_Hc + (size_t)((t+1)*BATCH + row)*VSZ + (j-1)*HID + (kr-512);
                    else
                        src = g_Hc + (size_t)(t*BATCH + row)*VSZ + j*HID + (kr-1024);
                    ra[q] = *(const float4*)src;
                }
            };
            auto loadB = [&](int kk) {
#pragma unroll
                for (int q = 0; q < 4; ++q) {
                    int p = tid + q*256, row = p >> 4, c4 = p & 15;
                    int gate = row >> 4;
                    int n = n0 + (row & 15);
                    int kc = kk + c4*4;
                    int kr = (j == 0 && kc >= 512) ? kc + 512 : kc;
                    rb[q] = *(const float4*)(g_Wt +
                        ((size_t)gate*NLAYER*HID + j*HID + n)*VSZ + kr);
                }
            };
            auto stsAB = [&](int b) {
                float* As_ = L_AS(b); float* Bs_ = L_BS(b);
#pragma unroll
                for (int q = 0; q < 2; ++q) {
                    int p = tid + q*256, row = p >> 4, c4 = p & 15;
                    *(float4*)(As_ + row*68 + c4*4) = ra[q];
                }
#pragma unroll
                for (int q = 0; q < 4; ++q) {
                    int p = tid + q*256, row = p >> 4, c4 = p & 15;
                    *(float4*)(Bs_ + row*68 + c4*4) = rb[q];
                }
            };

            loadA(0); loadB(0);
            stsAB(0);
            for (int kt = 0; kt < nk; ++kt) {
                if (kt + 1 < nk) { loadA((kt+1)*64); loadB((kt+1)*64); }
                __syncthreads();
                const float* As_ = L_AS(kt & 1);
                const float* Bs_ = L_BS(kt & 1);
#pragma unroll
                for (int k8 = 0; k8 < 8; ++k8) {
                    int kc = k8*8 + tq;
                    unsigned a0 = __float_as_uint(As_[(wm*16 + g)*68 + kc]);
                    unsigned a1 = __float_as_uint(As_[(wm*16 + g + 8)*68 + kc]);
                    unsigned a2 = __float_as_uint(As_[(wm*16 + g)*68 + kc + 4]);
                    unsigned a3 = __float_as_uint(As_[(wm*16 + g + 8)*68 + kc + 4]);
#pragma unroll
                    for (int nt = 0; nt < 2; ++nt) {
                        unsigned b0 = __float_as_uint(Bs_[(wn*16 + nt*8 + g)*68 + kc]);
                        unsigned b1 = __float_as_uint(Bs_[(wn*16 + nt*8 + g)*68 + kc + 4]);
                        mma8(acc[nt], a0, a1, a2, a3, b0, b1);
                    }
                }
                if (kt + 1 < nk) stsAB((kt + 1) & 1);
            }
#pragma unroll
            for (int nt = 0; nt < 2; ++nt) {
                int col = wn*16 + nt*8 + 2*tq;
                float* Cs_ = L_CS;
                Cs_[(wm*16 + g)*64 + col]         = acc[nt][0];
                Cs_[(wm*16 + g)*64 + col + 1]     = acc[nt][1];
                Cs_[(wm*16 + g + 8)*64 + col]     = acc[nt][2];
                Cs_[(wm*16 + g + 8)*64 + col + 1] = acc[nt][3];
            }
            __syncthreads();
            for (int p = tid; p < 512; p += 256) {
                int b = p >> 4, hc = p & 15;
                const float* Cs_ = L_CS;
                float zi = Cs_[b*64 + hc],      zf = Cs_[b*64 + 16 + hc];
                float zo = Cs_[b*64 + 32 + hc], zg = Cs_[b*64 + 48 + hc];
                float c = L_CST[p];
                float it = sigm(zi + L_PAR[hc]    + L_PAR[64+hc]*c);
                float ft = sigm(zf + L_PAR[16+hc] + L_PAR[80+hc]*c);
                float ct = it * tanhf(zg + L_PAR[48+hc]) + ft * c;
                float ot = sigm(zo + L_PAR[32+hc] + L_PAR[96+hc]*c); // peephole on OLD c
                float h  = ot * tanhf(ct);
                L_CST[p] = ct;
                g_Hc[(size_t)((t+1)*BATCH + b)*VSZ + j*HID + n0 + hc] = f2tff(h);
            }
        }
        // grid barrier
        __threadfence();
        __syncthreads();
        if (tid == 0) {
            unsigned arr = atomicAdd(&g_arrive, 1u) + 1u;
            if (arr == (unsigned)((w + 1) * LSTM_NCTA)) {
                atomicExch(&g_epoch, (unsigned)(w + 1));
            } else {
                volatile unsigned* ep = &g_epoch;
                while (*ep < (unsigned)(w + 1)) {}
                __threadfence();
            }
        }
        __syncthreads();
    }
}

// -------- tensor GEMM: C[M,N] = A[M,K] @ W[N,K]^T + bias --------
// BM=128, BN=256, BK=16, 256 thr, warps 2(M)x4(N), warp tile 64x64,
// 3-stage cp.async pipeline. Inputs must already be tf32-rounded.
#define G_AS 2560      // 128*20 floats
#define G_BS 5120      // 256*20 floats
#define G_STG (G_AS+G_BS)
#define GEMM_SMEM (3*G_STG*4)

__global__ void __launch_bounds__(256) gemm_tc(
    const float* __restrict__ A, int lda,
    const float* __restrict__ W, int ldw,
    const float* __restrict__ bias,
    float* __restrict__ C, int N, int K, int round_out)
{
    extern __shared__ float sm[];
    const int m0 = blockIdx.x * 128;
    const int n0 = blockIdx.y * 256;
    const int tid = threadIdx.x;
    const int warp = tid >> 5, lane = tid & 31;
    const int g = lane >> 2, tq = lane & 3;
    const int wm = warp & 1, wn = warp >> 1;

    auto issue = [&](int kt, int s) {
        int k0 = kt * 16;
        float* As_ = sm + s*G_STG;
        float* Bs_ = sm + s*G_STG + G_AS;
#pragma unroll
        for (int q = 0; q < 2; ++q) {
            int id = tid + q*256, r = id >> 2, c = (id & 3)*4;
            cpa16(scvt(As_ + r*20 + c), A + (size_t)(m0 + r)*lda + k0 + c, 16);
        }
#pragma unroll
        for (int q = 0; q < 4; ++q) {
            int id = tid + q*256, r = id >> 2, c = (id & 3)*4;
            int n = n0 + r;
            int ncl = (n < N) ? n : 0;
            int sz = (n < N) ? 16 : 0;
            cpa16(scvt(Bs_ + r*20 + c), W + (size_t)ncl*ldw + k0 + c, sz);
        }
        cpa_commit();
    };

    float acc[4][8][4] = {};
    const int nk = K >> 4;
    issue(0, 0); issue(1, 1);

    for (int kt = 0; kt < nk; ++kt) {
        asm volatile("cp.async.wait_group 1;" ::: "memory");
        __syncthreads();
        if (kt + 2 < nk) issue(kt + 2, (kt + 2) % 3);
        else cpa_commit();   // empty group keeps wait_group bookkeeping correct

        const float* As_ = sm + (kt % 3)*G_STG;
        const float* Bs_ = sm + (kt % 3)*G_STG + G_AS;
#pragma unroll
        for (int k8 = 0; k8 < 2; ++k8) {
            int kc = k8*8 + tq;
            unsigned a[4][4];
#pragma unroll
            for (int mf = 0; mf < 4; ++mf) {
                int r = wm*64 + mf*16 + g;
                a[mf][0] = __float_as_uint(As_[r*20 + kc]);
                a[mf][1] = __float_as_uint(As_[(r+8)*20 + kc]);
                a[mf][2] = __float_as_uint(As_[r*20 + kc + 4]);
                a[mf][3] = __float_as_uint(As_[(r+8)*20 + kc + 4]);
            }
#pragma unroll
            for (int nf = 0; nf < 8; ++nf) {
                int c = wn*64 + nf*8 + g;
                unsigned b0 = __float_as_uint(Bs_[c*20 + kc]);
                unsigned b1 = __float_as_uint(Bs_[c*20 + kc + 4]);
#pragma unroll
                for (int mf = 0; mf < 4; ++mf)
                    mma8(acc[mf][nf], a[mf][0], a[mf][1], a[mf][2], a[mf][3], b0, b1);
            }
        }
    }

#pragma unroll
    for (int mf = 0; mf < 4; ++mf) {
#pragma unroll
        for (int nf = 0; nf < 8; ++nf) {
            int r  = m0 + wm*64 + mf*16 + g;
            int cn = n0 + wn*64 + nf*8 + 2*tq;
            if (cn < N) {
                float v0 = acc[mf][nf][0] + bias[cn];
                float v2 = acc[mf][nf][2] + bias[cn];
                if (round_out) { v0 = f2tff(v0); v2 = f2tff(v2); }
                C[(size_t)r*N + cn]     = v0;
                C[(size_t)(r+8)*N + cn] = v2;
            }
            if (cn + 1 < N) {
                float v1 = acc[mf][nf][1] + bias[cn+1];
                float v3 = acc[mf][nf][3] + bias[cn+1];
                if (round_out) { v1 = f2tff(v1); v3 = f2tff(v3); }
                C[(size_t)r*N + cn + 1]     = v1;
                C[(size_t)(r+8)*N + cn + 1] = v3;
            }
        }
    }
}

extern "C" void kernel_launch(void* const* d_in, const int* in_sizes, int n_in,
                              void* d_out, int out_size) {
    const int*   ids  = (const int*)  d_in[0];
    const float* emb  = (const float*)d_in[1];
    const float* Wi   = (const float*)d_in[2];
    const float* bi   = (const float*)d_in[3];
    const float* Wf   = (const float*)d_in[4];
    const float* bf   = (const float*)d_in[5];
    const float* Wo   = (const float*)d_in[6];
    const float* bo   = (const float*)d_in[7];
    const float* Wg   = (const float*)d_in[8];
    const float* bg   = (const float*)d_in[9];
    const float* pci  = (const float*)d_in[10];
    const float* pcf  = (const float*)d_in[11];
    const float* pco  = (const float*)d_in[12];
    const float* Why  = (const float*)d_in[13];
    const float* bhy  = (const float*)d_in[14];
    const float* Wdec = (const float*)d_in[15];
    const float* bdec = (const float*)d_in[16];
    float* out = (float*)d_out;

    static int attr_done = 0;
    if (!attr_done) {
        cudaFuncSetAttribute(gemm_tc, cudaFuncAttributeMaxDynamicSharedMemorySize, GEMM_SMEM);
        cudaFuncSetAttribute(lstm_wave, cudaFuncAttributeMaxDynamicSharedMemorySize, LSTM_SMEM);
        attr_done = 1;
    }

    float *wt, *whyt, *wdect, *hc, *y;
    cudaGetSymbolAddress((void**)&wt,    g_Wt);
    cudaGetSymbolAddress((void**)&whyt,  g_WhyT);
    cudaGetSymbolAddress((void**)&wdect, g_WdecT);
    cudaGetSymbolAddress((void**)&hc,    g_Hc);
    cudaGetSymbolAddress((void**)&y,     g_y);

    const int GW = NLAYER*HID*VSZ;   // 2359296 per gate
    cvt_tf32<<<2048, 256>>>((const float4*)Wi,   (float4*)(wt + 0*(size_t)GW), GW/4);
    cvt_tf32<<<2048, 256>>>((const float4*)Wf,   (float4*)(wt + 1*(size_t)GW), GW/4);
    cvt_tf32<<<2048, 256>>>((const float4*)Wo,   (float4*)(wt + 2*(size_t)GW), GW/4);
    cvt_tf32<<<2048, 256>>>((const float4*)Wg,   (float4*)(wt + 3*(size_t)GW), GW/4);
    cvt_tf32<<<2048, 256>>>((const float4*)Why,  (float4*)whyt,  HID*VSZ/4);
    cvt_tf32<<<2048, 256>>>((const float4*)Wdec, (float4*)wdect, (int)((size_t)NVOC*HID/4));

    init_embed<<<MROWS + 16, 256>>>(ids, emb);
    lstm_wave<<<LSTM_NCTA, 256, LSTM_SMEM>>>(bi, bf, bo, bg, pci, pcf, pco);

    {   // y = Hcat @ Why^T + bhy  (M=4096, N=512, K=1536), output tf32-rounded
        dim3 grid(MROWS/128, (HID + 255)/256);
        gemm_tc<<<grid, 256, GEMM_SMEM>>>(hc + (size_t)BATCH*VSZ, VSZ,
                                          whyt, VSZ, bhy, y, HID, VSZ, 1);
    }
    {   // logits = y @ Wdec^T + bdec  (M=4096, N=50257, K=512)
        dim3 grid(MROWS/128, (NVOC + 255)/256);
        gemm_tc<<<grid, 256, GEMM_SMEM>>>(y, HID, wdect, HID, bdec,
                                          out, NVOC, HID, 0);
    }
}

// round 7
// speedup vs baseline: 2.0784x; 1.8212x over previous
#include <cuda_runtime.h>
#include <cuda_fp16.h>
#include <cstdint>
#include <cstddef>

#define S_LEN 128
#define BATCH 32
#define NIN   512
#define HID   512
#define NLAYER 3
#define VSZ   1536
#define NVOC  50257
#define MROWS (S_LEN*BATCH)
#define LSTM_NCTA 96

// -------- scratch (device globals; fp16 operands, fp32 state) --------
__device__ __half g_xh [MROWS*NIN];
__device__ __half g_Hch[(S_LEN+1)*BATCH*VSZ];
__device__ __half g_yh [MROWS*HID];
__device__ __half g_Wth[4*NLAYER*HID*VSZ];
__device__ __half g_WhyH[HID*VSZ];
__device__ __half g_WdecH[(size_t)NVOC*HID];
__device__ unsigned g_arrive;
__device__ unsigned g_epoch;

__device__ __forceinline__ float sigm(float x) { return 1.f / (1.f + expf(-x)); }
__device__ __forceinline__ unsigned scvt(const void* p) {
    return (unsigned)__cvta_generic_to_shared(p);
}
__device__ __forceinline__ void cpa16(unsigned d, const void* s, int sz) {
    asm volatile("cp.async.cg.shared.global [%0], [%1], 16, %2;"
                 :: "r"(d), "l"(s), "r"(sz));
}
__device__ __forceinline__ void cpa_commit() { asm volatile("cp.async.commit_group;"); }
__device__ __forceinline__ void ldm4(unsigned& r0, unsigned& r1, unsigned& r2,
                                     unsigned& r3, unsigned a) {
    asm volatile("ldmatrix.sync.aligned.m8n8.x4.shared.b16 {%0,%1,%2,%3}, [%4];"
                 : "=r"(r0), "=r"(r1), "=r"(r2), "=r"(r3) : "r"(a));
}
__device__ __forceinline__ void mma16(float* c, unsigned a0, unsigned a1,
                                      unsigned a2, unsigned a3,
                                      unsigned b0, unsigned b1) {
    asm volatile(
        "mma.sync.aligned.m16n8k16.row.col.f32.f16.f16.f32 "
        "{%0,%1,%2,%3}, {%4,%5,%6,%7}, {%8,%9}, {%0,%1,%2,%3};"
        : "+f"(c[0]), "+f"(c[1]), "+f"(c[2]), "+f"(c[3])
        : "r"(a0), "r"(a1), "r"(a2), "r"(a3), "r"(b0), "r"(b1));
}

// -------- fp16 pre-convert: 4 gate weight arrays --------
__global__ void __launch_bounds__(256) cvt_gates(
    const float4* __restrict__ Wi, const float4* __restrict__ Wf,
    const float4* __restrict__ Wo, const float4* __restrict__ Wg) {
    const int GW4 = NLAYER*HID*VSZ/4;
    __half2* dst = (__half2*)g_Wth;
    for (int i = blockIdx.x*256 + threadIdx.x; i < 4*GW4; i += gridDim.x*256) {
        int gate = i / GW4, k = i - gate*GW4;
        const float4* s = (gate == 0) ? Wi : (gate == 1) ? Wf : (gate == 2) ? Wo : Wg;
        float4 v = s[k];
        dst[2*i]   = __floats2half2_rn(v.x, v.y);
        dst[2*i+1] = __floats2half2_rn(v.z, v.w);
    }
}
// -------- fp16 pre-convert: Why + Wdec --------
__global__ void __launch_bounds__(256) cvt_out(const float4* __restrict__ Why,
                                               const float4* __restrict__ Wdec) {
    const int N1 = HID*VSZ/4;
    const int N2 = (int)((size_t)NVOC*HID/4);
    for (int i = blockIdx.x*256 + threadIdx.x; i < N1 + N2; i += gridDim.x*256) {
        float4 v; __half2* d;
        if (i < N1) { v = Why[i];      d = (__half2*)g_WhyH  + 2*i; }
        else        { v = Wdec[i-N1];  d = (__half2*)g_WdecH + 2*(size_t)(i-N1); }
        d[0] = __floats2half2_rn(v.x, v.y);
        d[1] = __floats2half2_rn(v.z, v.w);
    }
}

// -------- embed gather (fp16) + state init --------
__global__ void __launch_bounds__(256) init_embed(const int* __restrict__ ids,
                                                  const float* __restrict__ emb) {
    int blk = blockIdx.x;
    if (blk < MROWS) {
        int id = ids[blk];
        const float* src = emb + (size_t)id * NIN;
        __half* dst = g_xh + (size_t)blk * NIN;
        for (int k = threadIdx.x; k < NIN; k += 256) dst[k] = __float2half_rn(src[k]);
    } else {
        int z = blk - MROWS;   // 0..15 zero g_Hch slot 0 (49152 halves)
        for (int i = threadIdx.x; i < 3072; i += 256) g_Hch[(size_t)z*3072 + i] = __ushort_as_half(0);
        if (z == 0 && threadIdx.x == 0) { g_arrive = 0u; g_epoch = 0u; }
    }
}

// -------- persistent wavefront LSTM (fp16 mma, fp32 state) --------
__global__ void __launch_bounds__(256) lstm_wave(
    const float* __restrict__ bi, const float* __restrict__ bf,
    const float* __restrict__ bo, const float* __restrict__ bg,
    const float* __restrict__ pci, const float* __restrict__ pcf,
    const float* __restrict__ pco)
{
    __shared__ __half As[2][32*72];
    __shared__ __half Bs[2][64*72];
    __shared__ float  Cs[32*64];
    __shared__ float  cst[512];
    __shared__ float  par[112];

    const int cta = blockIdx.x;
    const int j   = cta >> 5;
    const int n0  = (cta & 31) * 16;
    const int tid = threadIdx.x;
    const int warp = tid >> 5, lane = tid & 31;
    const int wm = warp & 1;           // m half (16 rows)
    const int wn = warp >> 1;          // n quarter (16 cols)

    if (tid < 16) {
        int idx = j * HID + n0 + tid;
        par[tid]    = bi[idx];  par[16+tid] = bf[idx];
        par[32+tid] = bo[idx];  par[48+tid] = bg[idx];
        par[64+tid] = pci[idx]; par[80+tid] = pcf[idx];
        par[96+tid] = pco[idx];
    }
    for (int i = tid; i < 512; i += 256) cst[i] = 0.f;
    __syncthreads();

    const int Keff = (j == 0) ? 1024 : 1536;   // layer0 prev-h block is zero: skip
    const int nk = Keff >> 6;                  // BK = 64 halves

    for (int w = 0; w < S_LEN + NLAYER - 1; ++w) {
        const int t = w - j;
        if (t >= 0 && t < S_LEN) {
            float acc[2][4] = {};
            float4 ra, rb[2];

            auto loadA = [&](int kk) {
                int r = tid >> 3, c8 = tid & 7;
                int kc = kk + c8*8;
                int kr = (j == 0 && kc >= 512) ? kc + 512 : kc;
                const __half* src;
                if (kr < 512)
                    src = g_xh + (size_t)(t*BATCH + r)*NIN + kr;
                else if (kr < 1024)
                    src = g_Hch + (size_t)((t+1)*BATCH + r)*VSZ + (j-1)*HID + (kr-512);
                else
                    src = g_Hch + (size_t)(t*BATCH + r)*VSZ + j*HID + (kr-1024);
                ra = *(const float4*)src;
            };
            auto loadB = [&](int kk) {
#pragma unroll
                for (int q = 0; q < 2; ++q) {
                    int id = tid + q*256, r = id >> 3, c8 = id & 7;
                    int gate = r >> 4;
                    int n = n0 + (r & 15);
                    int kc = kk + c8*8;
                    int kr = (j == 0 && kc >= 512) ? kc + 512 : kc;
                    rb[q] = *(const float4*)(g_Wth +
                        ((size_t)gate*NLAYER*HID + j*HID + n)*VSZ + kr);
                }
            };
            auto stsAB = [&](int b) {
                {
                    int r = tid >> 3, c8 = tid & 7;
                    *(float4*)(&As[b][r*72 + c8*8]) = ra;
                }
#pragma unroll
                for (int q = 0; q < 2; ++q) {
                    int id = tid + q*256, r = id >> 3, c8 = id & 7;
                    *(float4*)(&Bs[b][r*72 + c8*8]) = rb[q];
                }
            };

            loadA(0); loadB(0);
            stsAB(0);
            for (int kt = 0; kt < nk; ++kt) {
                if (kt + 1 < nk) { loadA((kt+1)*64); loadB((kt+1)*64); }
                __syncthreads();
                const int buf = kt & 1;
#pragma unroll
                for (int ks = 0; ks < 4; ++ks) {
                    unsigned a0, a1, a2, a3, b0, b1, b2, b3;
                    unsigned aad = scvt(&As[buf][(wm*16 + (lane & 15))*72
                                                 + ks*16 + ((lane >> 4) << 3)]);
                    ldm4(a0, a1, a2, a3, aad);
                    unsigned bad = scvt(&Bs[buf][(wn*16 + ((lane >> 4) << 3) + (lane & 7))*72
                                                 + ks*16 + (((lane >> 3) & 1) << 3)]);
                    ldm4(b0, b1, b2, b3, bad);
                    mma16(acc[0], a0, a1, a2, a3, b0, b1);
                    mma16(acc[1], a0, a1, a2, a3, b2, b3);
                }
                if (kt + 1 < nk) stsAB((kt + 1) & 1);
            }
#pragma unroll
            for (int nf = 0; nf < 2; ++nf) {
                int row = wm*16 + (lane >> 2);
                int col = wn*16 + nf*8 + (lane & 3)*2;
                Cs[row*64 + col]       = acc[nf][0];
                Cs[row*64 + col + 1]   = acc[nf][1];
                Cs[(row+8)*64 + col]   = acc[nf][2];
                Cs[(row+8)*64 + col+1] = acc[nf][3];
            }
            __syncthreads();
            for (int p = tid; p < 512; p += 256) {
                int b = p >> 4, hc = p & 15;
                float zi = Cs[b*64 + hc],      zf = Cs[b*64 + 16 + hc];
                float zo = Cs[b*64 + 32 + hc], zg = Cs[b*64 + 48 + hc];
                float c = cst[p];
                float it = sigm(zi + par[hc]    + par[64+hc]*c);
                float ft = sigm(zf + par[16+hc] + par[80+hc]*c);
                float ct = it * tanhf(zg + par[48+hc]) + ft * c;
                float ot = sigm(zo + par[32+hc] + par[96+hc]*c);  // peephole on OLD c
                float h  = ot * tanhf(ct);
                cst[p] = ct;
                g_Hch[(size_t)((t+1)*BATCH + b)*VSZ + j*HID + n0 + hc] = __float2half_rn(h);
            }
        }
        // ---- grid barrier ----
        __threadfence();
        __syncthreads();
        if (tid == 0) {
            unsigned arr = atomicAdd(&g_arrive, 1u) + 1u;
            if (arr == (unsigned)((w + 1) * LSTM_NCTA)) {
                atomicExch(&g_epoch, (unsigned)(w + 1));
            } else {
                volatile unsigned* ep = &g_epoch;
                while (*ep < (unsigned)(w + 1)) {}
                __threadfence();
            }
        }
        __syncthreads();
    }
}

// -------- fp16 tensor GEMM: C[M,N] = A[M,K] @ W[N,K]^T + bias --------
// BM=128, BN=256, BK=64 halves, 3-stage cp.async ring, 8 warps (2m x 4n),
// warp tile 64x64, ldmatrix fragments, fp32 accumulate.
#define GH_LD   72
#define GH_AB   (128*GH_LD*2)          // 18432 B
#define GH_BB   (256*GH_LD*2)          // 36864 B
#define GH_STG  (GH_AB + GH_BB)        // 55296 B
#define GH_SMEM (3*GH_STG)             // 165888 B

__global__ void __launch_bounds__(256)
gemm_h(const __half* __restrict__ A, int lda,
       const __half* __restrict__ W, int ldw,
       const float* __restrict__ bias,
       float* __restrict__ Cf, __half* __restrict__ Ch, int out_half,
       int N, int K)
{
    extern __shared__ char smg[];
    const int tid = threadIdx.x;
    const int warp = tid >> 5, lane = tid & 31;
    const int wm = warp & 1, wn = warp >> 1;
    const int m0 = blockIdx.x * 128;
    const int n0 = blockIdx.y * 256;
    const int nk = K >> 6;

    auto fill = [&](int c, int s) {
        int k0 = c << 6;
        char* sA = smg + s*GH_STG;
        char* sB = sA + GH_AB;
#pragma unroll
        for (int q = 0; q < 4; ++q) {          // A: 128 rows x 8 chunks
            int id = tid + q*256, r = id >> 3, c16 = id & 7;
            cpa16(scvt(sA + (r*GH_LD + c16*8)*2),
                  A + (size_t)(m0 + r)*lda + k0 + c16*8, 16);
        }
#pragma unroll
        for (int q = 0; q < 8; ++q) {          // B: 256 rows x 8 chunks
            int id = tid + q*256, r = id >> 3, c16 = id & 7;
            int n = n0 + r;
            int ncl = (n < N) ? n : 0;
            int sz = (n < N) ? 16 : 0;
            cpa16(scvt(sB + (r*GH_LD + c16*8)*2),
                  W + (size_t)ncl*ldw + k0 + c16*8, sz);
        }
        cpa_commit();
    };

    float acc[4][8][4] = {};
    fill(0, 0); fill(1, 1);

    for (int c = 0; c < nk; ++c) {
        asm volatile("cp.async.wait_group 1;" ::: "memory");
        __syncthreads();
        if (c + 2 < nk) fill(c + 2, (c + 2) % 3);
        else cpa_commit();

        const char* sA = smg + (c % 3)*GH_STG;
        const char* sB = sA + GH_AB;
#pragma unroll
        for (int ks = 0; ks < 4; ++ks) {
            unsigned a[4][4], b[8][2];
#pragma unroll
            for (int mf = 0; mf < 4; ++mf) {
                unsigned ad = scvt(sA + ((wm*64 + mf*16 + (lane & 15))*GH_LD
                                         + ks*16 + ((lane >> 4) << 3))*2);
                ldm4(a[mf][0], a[mf][1], a[mf][2], a[mf][3], ad);
            }
#pragma unroll
            for (int np = 0; np < 4; ++np) {
                unsigned bd = scvt(sB + ((wn*64 + np*16 + ((lane >> 4) << 3) + (lane & 7))*GH_LD
                                         + ks*16 + (((lane >> 3) & 1) << 3))*2);
                ldm4(b[2*np][0], b[2*np][1], b[2*np+1][0], b[2*np+1][1], bd);
            }
#pragma unroll
            for (int nf = 0; nf < 8; ++nf)
#pragma unroll
                for (int mf = 0; mf < 4; ++mf)
                    mma16(acc[mf][nf], a[mf][0], a[mf][1], a[mf][2], a[mf][3],
                          b[nf][0], b[nf][1]);
        }
    }

#pragma unroll
    for (int mf = 0; mf < 4; ++mf) {
#pragma unroll
        for (int nf = 0; nf < 8; ++nf) {
            int r  = m0 + wm*64 + mf*16 + (lane >> 2);
            int cn = n0 + wn*64 + nf*8 + (lane & 3)*2;
#pragma unroll
            for (int h2 = 0; h2 < 2; ++h2) {
                int rr = r + h2*8;
                float v0 = acc[mf][nf][2*h2]     + ((cn < N) ? bias[cn] : 0.f);
                float v1 = acc[mf][nf][2*h2 + 1] + ((cn+1 < N) ? bias[cn+1] : 0.f);
                if (out_half) {
                    if (cn < N)     Ch[(size_t)rr*N + cn]     = __float2half_rn(v0);
                    if (cn + 1 < N) Ch[(size_t)rr*N + cn + 1] = __float2half_rn(v1);
                } else {
                    if (cn < N)     Cf[(size_t)rr*N + cn]     = v0;
                    if (cn + 1 < N) Cf[(size_t)rr*N + cn + 1] = v1;
                }
            }
        }
    }
}

extern "C" void kernel_launch(void* const* d_in, const int* in_sizes, int n_in,
                              void* d_out, int out_size) {
    const int*   ids  = (const int*)  d_in[0];
    const float* emb  = (const float*)d_in[1];
    const float* Wi   = (const float*)d_in[2];
    const float* bi   = (const float*)d_in[3];
    const float* Wf   = (const float*)d_in[4];
    const float* bf   = (const float*)d_in[5];
    const float* Wo   = (const float*)d_in[6];
    const float* bo   = (const float*)d_in[7];
    const float* Wg   = (const float*)d_in[8];
    const float* bg   = (const float*)d_in[9];
    const float* pci  = (const float*)d_in[10];
    const float* pcf  = (const float*)d_in[11];
    const float* pco  = (const float*)d_in[12];
    const float* Why  = (const float*)d_in[13];
    const float* bhy  = (const float*)d_in[14];
    const float* Wdec = (const float*)d_in[15];
    const float* bdec = (const float*)d_in[16];
    float* out = (float*)d_out;

    cudaFuncSetAttribute(gemm_h, cudaFuncAttributeMaxDynamicSharedMemorySize, GH_SMEM);

    __half *whyh, *wdech, *hch, *yh;
    cudaGetSymbolAddress((void**)&whyh,  g_WhyH);
    cudaGetSymbolAddress((void**)&wdech, g_WdecH);
    cudaGetSymbolAddress((void**)&hch,   g_Hch);
    cudaGetSymbolAddress((void**)&yh,    g_yh);

    cvt_gates<<<2048, 256>>>((const float4*)Wi, (const float4*)Wf,
                             (const float4*)Wo, (const float4*)Wg);
    cvt_out<<<2048, 256>>>((const float4*)Why, (const float4*)Wdec);
    init_embed<<<MROWS + 16, 256>>>(ids, emb);
    lstm_wave<<<LSTM_NCTA, 256>>>(bi, bf, bo, bg, pci, pcf, pco);

    {   // y = Hcat @ Why^T + bhy  (M=4096, N=512, K=1536) -> fp16 y
        dim3 grid(MROWS/128, (HID + 255)/256);
        gemm_h<<<grid, 256, GH_SMEM>>>(hch + (size_t)BATCH*VSZ, VSZ,
                                       whyh, VSZ, bhy, nullptr, yh, 1, HID, VSZ);
    }
    {   // logits = y @ Wdec^T + bdec  (M=4096, N=50257, K=512) -> fp32 out
        dim3 grid(MROWS/128, (NVOC + 255)/256);
        gemm_h<<<grid, 256, GH_SMEM>>>(yh, HID, wdech, HID, bdec,
                                       out, nullptr, 0, NVOC, HID);
    }
}

// round 12
// speedup vs baseline: 2.1875x; 1.0525x over previous
#include <cuda_runtime.h>
#include <cuda_fp16.h>
#include <cstdint>
#include <cstddef>

#define S_LEN 128
#define BATCH 32
#define NIN   512
#define HID   512
#define NLAYER 3
#define VSZ   1536
#define NVOC  50257
#define MROWS (S_LEN*BATCH)
#define LSTM_NCTA 96

// -------- scratch (device globals; fp16 operands, fp32 state) --------
__device__ __half g_xh [MROWS*NIN];
__device__ __half g_Hch[(S_LEN+1)*BATCH*VSZ];
__device__ __half g_yh [MROWS*HID];
__device__ __half g_Wth[4*NLAYER*HID*VSZ];
__device__ __half g_WhyH[HID*VSZ];
__device__ __half g_WdecH[(size_t)NVOC*HID];
__device__ unsigned g_arrive;
__device__ unsigned g_epoch;

__device__ __forceinline__ float sigm(float x) { return 1.f / (1.f + expf(-x)); }
__device__ __forceinline__ unsigned scvt(const void* p) {
    return (unsigned)__cvta_generic_to_shared(p);
}
__device__ __forceinline__ void cpa16(unsigned d, const void* s, int sz) {
    asm volatile("cp.async.cg.shared.global [%0], [%1], 16, %2;"
                 :: "r"(d), "l"(s), "r"(sz));
}
__device__ __forceinline__ void cpa_commit() { asm volatile("cp.async.commit_group;"); }
__device__ __forceinline__ void ldm4(unsigned& r0, unsigned& r1, unsigned& r2,
                                     unsigned& r3, unsigned a) {
    asm volatile("ldmatrix.sync.aligned.m8n8.x4.shared.b16 {%0,%1,%2,%3}, [%4];"
                 : "=r"(r0), "=r"(r1), "=r"(r2), "=r"(r3) : "r"(a));
}
__device__ __forceinline__ void mma16(float* c, unsigned a0, unsigned a1,
                                      unsigned a2, unsigned a3,
                                      unsigned b0, unsigned b1) {
    asm volatile(
        "mma.sync.aligned.m16n8k16.row.col.f32.f16.f16.f32 "
        "{%0,%1,%2,%3}, {%4,%5,%6,%7}, {%8,%9}, {%0,%1,%2,%3};"
        : "+f"(c[0]), "+f"(c[1]), "+f"(c[2]), "+f"(c[3])
        : "r"(a0), "r"(a1), "r"(a2), "r"(a3), "r"(b0), "r"(b1));
}

// -------- fp16 pre-convert: 4 gate weight arrays --------
__global__ void __launch_bounds__(256) cvt_gates(
    const float4* __restrict__ Wi, const float4* __restrict__ Wf,
    const float4* __restrict__ Wo, const float4* __restrict__ Wg) {
    const int GW4 = NLAYER*HID*VSZ/4;
    __half2* dst = (__half2*)g_Wth;
    for (int i = blockIdx.x*256 + threadIdx.x; i < 4*GW4; i += gridDim.x*256) {
        int gate = i / GW4, k = i - gate*GW4;
        const float4* s = (gate == 0) ? Wi : (gate == 1) ? Wf : (gate == 2) ? Wo : Wg;
        float4 v = s[k];
        dst[2*i]   = __floats2half2_rn(v.x, v.y);
        dst[2*i+1] = __floats2half2_rn(v.z, v.w);
    }
}
// -------- fp16 pre-convert: Why + Wdec --------
__global__ void __launch_bounds__(256) cvt_out(const float4* __restrict__ Why,
                                               const float4* __restrict__ Wdec) {
    const int N1 = HID*VSZ/4;
    const int N2 = (int)((size_t)NVOC*HID/4);
    for (int i = blockIdx.x*256 + threadIdx.x; i < N1 + N2; i += gridDim.x*256) {
        float4 v; __half2* d;
        if (i < N1) { v = Why[i];      d = (__half2*)g_WhyH  + 2*i; }
        else        { v = Wdec[i-N1];  d = (__half2*)g_WdecH + 2*(size_t)(i-N1); }
        d[0] = __floats2half2_rn(v.x, v.y);
        d[1] = __floats2half2_rn(v.z, v.w);
    }
}

// -------- embed gather (fp16) + state init --------
__global__ void __launch_bounds__(256) init_embed(const int* __restrict__ ids,
                                                  const float* __restrict__ emb) {
    int blk = blockIdx.x;
    if (blk < MROWS) {
        int id = ids[blk];
        const float* src = emb + (size_t)id * NIN;
        __half* dst = g_xh + (size_t)blk * NIN;
        for (int k = threadIdx.x; k < NIN; k += 256) dst[k] = __float2half_rn(src[k]);
    } else {
        int z = blk - MROWS;   // zero g_Hch slot 0
        for (int i = threadIdx.x; i < 3072; i += 256)
            g_Hch[(size_t)z*3072 + i] = __ushort_as_half((unsigned short)0);
        if (z == 0 && threadIdx.x == 0) { g_arrive = 0u; g_epoch = 0u; }
    }
}

// -------- persistent wavefront LSTM (exact R7 version — known good) --------
__global__ void __launch_bounds__(256) lstm_wave(
    const float* __restrict__ bi, const float* __restrict__ bf,
    const float* __restrict__ bo, const float* __restrict__ bg,
    const float* __restrict__ pci, const float* __restrict__ pcf,
    const float* __restrict__ pco)
{
    __shared__ __half As[2][32*72];
    __shared__ __half Bs[2][64*72];
    __shared__ float  Cs[32*64];
    __shared__ float  cst[512];
    __shared__ float  par[112];

    const int cta = blockIdx.x;
    const int j   = cta >> 5;
    const int n0  = (cta & 31) * 16;
    const int tid = threadIdx.x;
    const int warp = tid >> 5, lane = tid & 31;
    const int wm = warp & 1;
    const int wn = warp >> 1;

    if (tid < 16) {
        int idx = j * HID + n0 + tid;
        par[tid]    = bi[idx];  par[16+tid] = bf[idx];
        par[32+tid] = bo[idx];  par[48+tid] = bg[idx];
        par[64+tid] = pci[idx]; par[80+tid] = pcf[idx];
        par[96+tid] = pco[idx];
    }
    for (int i = tid; i < 512; i += 256) cst[i] = 0.f;
    __syncthreads();

    const int Keff = (j == 0) ? 1024 : 1536;
    const int nk = Keff >> 6;

    for (int w = 0; w < S_LEN + NLAYER - 1; ++w) {
        const int t = w - j;
        if (t >= 0 && t < S_LEN) {
            float acc[2][4] = {};
            float4 ra, rb[2];

            auto loadA = [&](int kk) {
                int r = tid >> 3, c8 = tid & 7;
                int kc = kk + c8*8;
                int kr = (j == 0 && kc >= 512) ? kc + 512 : kc;
                const __half* src;
                if (kr < 512)
                    src = g_xh + (size_t)(t*BATCH + r)*NIN + kr;
                else if (kr < 1024)
                    src = g_Hch + (size_t)((t+1)*BATCH + r)*VSZ + (j-1)*HID + (kr-512);
                else
                    src = g_Hch + (size_t)(t*BATCH + r)*VSZ + j*HID + (kr-1024);
                ra = *(const float4*)src;
            };
            auto loadB = [&](int kk) {
#pragma unroll
                for (int q = 0; q < 2; ++q) {
                    int id = tid + q*256, r = id >> 3, c8 = id & 7;
                    int gate = r >> 4;
                    int n = n0 + (r & 15);
                    int kc = kk + c8*8;
                    int kr = (j == 0 && kc >= 512) ? kc + 512 : kc;
                    rb[q] = *(const float4*)(g_Wth +
                        ((size_t)gate*NLAYER*HID + j*HID + n)*VSZ + kr);
                }
            };
            auto stsAB = [&](int b) {
                {
                    int r = tid >> 3, c8 = tid & 7;
                    *(float4*)(&As[b][r*72 + c8*8]) = ra;
                }
#pragma unroll
                for (int q = 0; q < 2; ++q) {
                    int id = tid + q*256, r = id >> 3, c8 = id & 7;
                    *(float4*)(&Bs[b][r*72 + c8*8]) = rb[q];
                }
            };

            loadA(0); loadB(0);
            stsAB(0);
            for (int kt = 0; kt < nk; ++kt) {
                if (kt + 1 < nk) { loadA((kt+1)*64); loadB((kt+1)*64); }
                __syncthreads();
                const int buf = kt & 1;
#pragma unroll
                for (int ks = 0; ks < 4; ++ks) {
                    unsigned a0, a1, a2, a3, b0, b1, b2, b3;
                    unsigned aad = scvt(&As[buf][(wm*16 + (lane & 15))*72
                                                 + ks*16 + ((lane >> 4) << 3)]);
                    ldm4(a0, a1, a2, a3, aad);
                    unsigned bad = scvt(&Bs[buf][(wn*16 + ((lane >> 4) << 3) + (lane & 7))*72
                                                 + ks*16 + (((lane >> 3) & 1) << 3)]);
                    ldm4(b0, b1, b2, b3, bad);
                    mma16(acc[0], a0, a1, a2, a3, b0, b1);
                    mma16(acc[1], a0, a1, a2, a3, b2, b3);
                }
                if (kt + 1 < nk) stsAB((kt + 1) & 1);
            }
#pragma unroll
            for (int nf = 0; nf < 2; ++nf) {
                int row = wm*16 + (lane >> 2);
                int col = wn*16 + nf*8 + (lane & 3)*2;
                Cs[row*64 + col]       = acc[nf][0];
                Cs[row*64 + col + 1]   = acc[nf][1];
                Cs[(row+8)*64 + col]   = acc[nf][2];
                Cs[(row+8)*64 + col+1] = acc[nf][3];
            }
            __syncthreads();
            for (int p = tid; p < 512; p += 256) {
                int b = p >> 4, hc = p & 15;
                float zi = Cs[b*64 + hc],      zf = Cs[b*64 + 16 + hc];
                float zo = Cs[b*64 + 32 + hc], zg = Cs[b*64 + 48 + hc];
                float c = cst[p];
                float it = sigm(zi + par[hc]    + par[64+hc]*c);
                float ft = sigm(zf + par[16+hc] + par[80+hc]*c);
                float ct = it * tanhf(zg + par[48+hc]) + ft * c;
                float ot = sigm(zo + par[32+hc] + par[96+hc]*c);  // peephole on OLD c
                float h  = ot * tanhf(ct);
                cst[p] = ct;
                g_Hch[(size_t)((t+1)*BATCH + b)*VSZ + j*HID + n0 + hc] = __float2half_rn(h);
            }
        }
        // ---- grid barrier ----
        __threadfence();
        __syncthreads();
        if (tid == 0) {
            unsigned arr = atomicAdd(&g_arrive, 1u) + 1u;
            if (arr == (unsigned)((w + 1) * LSTM_NCTA)) {
                atomicExch(&g_epoch, (unsigned)(w + 1));
            } else {
                volatile unsigned* ep = &g_epoch;
                while (*ep < (unsigned)(w + 1)) {}
                __threadfence();
            }
        }
        __syncthreads();
    }
}

// -------- fp16 tensor GEMM: C[M,N] = A[M,K] @ W[N,K]^T + bias --------
// BM=128, BN=128, BK=64, 3-stage cp.async ring, 8 warps (2m x 4n),
// warp tile 64x32, 2 CTAs/SM.
#define GH_LD   72
#define GH_AB   (128*GH_LD*2)
#define GH_BB   (128*GH_LD*2)
#define GH_STG  (GH_AB + GH_BB)        // 36864 B
#define GH_SMEM (3*GH_STG)             // 110592 B

__global__ void __launch_bounds__(256, 2)
gemm_h(const __half* __restrict__ A, int lda,
       const __half* __restrict__ W, int ldw,
       const float* __restrict__ bias,
       float* __restrict__ Cf, __half* __restrict__ Ch, int out_half,
       int N, int K)
{
    extern __shared__ char smg[];
    const int tid = threadIdx.x;
    const int warp = tid >> 5, lane = tid & 31;
    const int wm = warp & 1, wn = warp >> 1;
    const int m0 = blockIdx.x * 128;
    const int n0 = blockIdx.y * 128;
    const int nk = K >> 6;

    auto fill = [&](int c, int s) {
        int k0 = c << 6;
        char* sA = smg + s*GH_STG;
        char* sB = sA + GH_AB;
#pragma unroll
        for (int q = 0; q < 4; ++q) {
            int id = tid + q*256, r = id >> 3, c16 = id & 7;
            cpa16(scvt(sA + (r*GH_LD + c16*8)*2),
                  A + (size_t)(m0 + r)*lda + k0 + c16*8, 16);
        }
#pragma unroll
        for (int q = 0; q < 4; ++q) {
            int id = tid + q*256, r = id >> 3, c16 = id & 7;
            int n = n0 + r;
            int ncl = (n < N) ? n : 0;
            int sz = (n < N) ? 16 : 0;
            cpa16(scvt(sB + (r*GH_LD + c16*8)*2),
                  W + (size_t)ncl*ldw + k0 + c16*8, sz);
        }
        cpa_commit();
    };

    float acc[4][4][4] = {};
    fill(0, 0); fill(1, 1);

    for (int c = 0; c < nk; ++c) {
        asm volatile("cp.async.wait_group 1;" ::: "memory");
        __syncthreads();
        if (c + 2 < nk) fill(c + 2, (c + 2) % 3);
        else cpa_commit();

        const char* sA = smg + (c % 3)*GH_STG;
        const char* sB = sA + GH_AB;
#pragma unroll
        for (int ks = 0; ks < 4; ++ks) {
            unsigned a[4][4], b[4][2];
#pragma unroll
            for (int mf = 0; mf < 4; ++mf) {
                unsigned ad = scvt(sA + ((wm*64 + mf*16 + (lane & 15))*GH_LD
                                         + ks*16 + ((lane >> 4) << 3))*2);
                ldm4(a[mf][0], a[mf][1], a[mf][2], a[mf][3], ad);
            }
#pragma unroll
            for (int np = 0; np < 2; ++np) {
                unsigned bd = scvt(sB + ((wn*32 + np*16 + ((lane >> 4) << 3) + (lane & 7))*GH_LD
                                         + ks*16 + (((lane >> 3) & 1) << 3))*2);
                ldm4(b[2*np][0], b[2*np][1], b[2*np+1][0], b[2*np+1][1], bd);
            }
#pragma unroll
            for (int nf = 0; nf < 4; ++nf)
#pragma unroll
                for (int mf = 0; mf < 4; ++mf)
                    mma16(acc[mf][nf], a[mf][0], a[mf][1], a[mf][2], a[mf][3],
                          b[nf][0], b[nf][1]);
        }
    }

#pragma unroll
    for (int mf = 0; mf < 4; ++mf) {
#pragma unroll
        for (int nf = 0; nf < 4; ++nf) {
            int r  = m0 + wm*64 + mf*16 + (lane >> 2);
            int cn = n0 + wn*32 + nf*8 + (lane & 3)*2;
#pragma unroll
            for (int h2 = 0; h2 < 2; ++h2) {
                int rr = r + h2*8;
                float v0 = acc[mf][nf][2*h2]     + ((cn < N) ? bias[cn] : 0.f);
                float v1 = acc[mf][nf][2*h2 + 1] + ((cn+1 < N) ? bias[cn+1] : 0.f);
                if (out_half) {
                    if (cn < N)     Ch[(size_t)rr*N + cn]     = __float2half_rn(v0);
                    if (cn + 1 < N) Ch[(size_t)rr*N + cn + 1] = __float2half_rn(v1);
                } else {
                    if (cn < N)     Cf[(size_t)rr*N + cn]     = v0;
                    if (cn + 1 < N) Cf[(size_t)rr*N + cn + 1] = v1;
                }
            }
        }
    }
}

extern "C" void kernel_launch(void* const* d_in, const int* in_sizes, int n_in,
                              void* d_out, int out_size) {
    const int*   ids  = (const int*)  d_in[0];
    const float* emb  = (const float*)d_in[1];
    const float* Wi   = (const float*)d_in[2];
    const float* bi   = (const float*)d_in[3];
    const float* Wf   = (const float*)d_in[4];
    const float* bf   = (const float*)d_in[5];
    const float* Wo   = (const float*)d_in[6];
    const float* bo   = (const float*)d_in[7];
    const float* Wg   = (const float*)d_in[8];
    const float* bg   = (const float*)d_in[9];
    const float* pci  = (const float*)d_in[10];
    const float* pcf  = (const float*)d_in[11];
    const float* pco  = (const float*)d_in[12];
    const float* Why  = (const float*)d_in[13];
    const float* bhy  = (const float*)d_in[14];
    const float* Wdec = (const float*)d_in[15];
    const float* bdec = (const float*)d_in[16];
    float* out = (float*)d_out;

    cudaFuncSetAttribute(gemm_h, cudaFuncAttributeMaxDynamicSharedMemorySize, GH_SMEM);

    __half *whyh, *wdech, *hch, *yh;
    cudaGetSymbolAddress((void**)&whyh,  g_WhyH);
    cudaGetSymbolAddress((void**)&wdech, g_WdecH);
    cudaGetSymbolAddress((void**)&hch,   g_Hch);
    cudaGetSymbolAddress((void**)&yh,    g_yh);

    cvt_gates<<<2048, 256>>>((const float4*)Wi, (const float4*)Wf,
                             (const float4*)Wo, (const float4*)Wg);
    cvt_out<<<2048, 256>>>((const float4*)Why, (const float4*)Wdec);
    init_embed<<<MROWS + 16, 256>>>(ids, emb);
    lstm_wave<<<LSTM_NCTA, 256>>>(bi, bf, bo, bg, pci, pcf, pco);

    {   // y = Hcat @ Why^T + bhy  (M=4096, N=512, K=1536) -> fp16 y
        dim3 grid(MROWS/128, (HID + 127)/128);
        gemm_h<<<grid, 256, GH_SMEM>>>(hch + (size_t)BATCH*VSZ, VSZ,
                                       whyh, VSZ, bhy, nullptr, yh, 1, HID, VSZ);
    }
    {   // logits = y @ Wdec^T + bdec  (M=4096, N=50257, K=512) -> fp32 out
        dim3 grid(MROWS/128, (NVOC + 127)/128);
        gemm_h<<<grid, 256, GH_SMEM>>>(yh, HID, wdech, HID, bdec,
                                       out, nullptr, 0, NVOC, HID);
    }
}

// round 13
// speedup vs baseline: 2.3699x; 1.0834x over previous
#include <cuda_runtime.h>
#include <cuda_fp16.h>
#include <cstdint>
#include <cstddef>

#define S_LEN 128
#define BATCH 32
#define NIN   512
#define HID   512
#define NLAYER 3
#define VSZ   1536
#define NVOC  50257
#define MROWS (S_LEN*BATCH)
#define LSTM_NCTA 96

// -------- scratch (device globals; fp16 operands, fp32 state) --------
__device__ __half g_xh [MROWS*NIN];
__device__ __half g_Hch[(S_LEN+1)*BATCH*VSZ];
__device__ __half g_yh [MROWS*HID];
__device__ __half g_WhyH[HID*VSZ];
__device__ __half g_WdecH[(size_t)NVOC*HID];
__device__ unsigned g_arrive;
__device__ unsigned g_epoch;

__device__ __forceinline__ float sigm(float x) { return 1.f / (1.f + expf(-x)); }
__device__ __forceinline__ unsigned scvt(const void* p) {
    return (unsigned)__cvta_generic_to_shared(p);
}
__device__ __forceinline__ void cpa16(unsigned d, const void* s, int sz) {
    asm volatile("cp.async.cg.shared.global [%0], [%1], 16, %2;"
                 :: "r"(d), "l"(s), "r"(sz));
}
__device__ __forceinline__ void cpa_commit() { asm volatile("cp.async.commit_group;"); }
__device__ __forceinline__ void ldm4(unsigned& r0, unsigned& r1, unsigned& r2,
                                     unsigned& r3, unsigned a) {
    asm volatile("ldmatrix.sync.aligned.m8n8.x4.shared.b16 {%0,%1,%2,%3}, [%4];"
                 : "=r"(r0), "=r"(r1), "=r"(r2), "=r"(r3) : "r"(a));
}
__device__ __forceinline__ void mma16(float* c, unsigned a0, unsigned a1,
                                      unsigned a2, unsigned a3,
                                      unsigned b0, unsigned b1) {
    asm volatile(
        "mma.sync.aligned.m16n8k16.row.col.f32.f16.f16.f32 "
        "{%0,%1,%2,%3}, {%4,%5,%6,%7}, {%8,%9}, {%0,%1,%2,%3};"
        : "+f"(c[0]), "+f"(c[1]), "+f"(c[2]), "+f"(c[3])
        : "r"(a0), "r"(a1), "r"(a2), "r"(a3), "r"(b0), "r"(b1));
}

// -------- fp16 pre-convert: Why + Wdec --------
__global__ void __launch_bounds__(256) cvt_out(const float4* __restrict__ Why,
                                               const float4* __restrict__ Wdec) {
    const int N1 = HID*VSZ/4;
    const int N2 = (int)((size_t)NVOC*HID/4);
    for (int i = blockIdx.x*256 + threadIdx.x; i < N1 + N2; i += gridDim.x*256) {
        float4 v; __half2* d;
        if (i < N1) { v = Why[i];      d = (__half2*)g_WhyH  + 2*i; }
        else        { v = Wdec[i-N1];  d = (__half2*)g_WdecH + 2*(size_t)(i-N1); }
        d[0] = __floats2half2_rn(v.x, v.y);
        d[1] = __floats2half2_rn(v.z, v.w);
    }
}

// -------- embed gather (fp16) + state init --------
__global__ void __launch_bounds__(256) init_embed(const int* __restrict__ ids,
                                                  const float* __restrict__ emb) {
    int blk = blockIdx.x;
    if (blk < MROWS) {
        int id = ids[blk];
        const float* src = emb + (size_t)id * NIN;
        __half* dst = g_xh + (size_t)blk * NIN;
        for (int k = threadIdx.x; k < NIN; k += 256) dst[k] = __float2half_rn(src[k]);
    } else {
        int z = blk - MROWS;   // zero g_Hch slot 0
        for (int i = threadIdx.x; i < 3072; i += 256)
            g_Hch[(size_t)z*3072 + i] = __ushort_as_half((unsigned short)0);
        if (z == 0 && threadIdx.x == 0) { g_arrive = 0u; g_epoch = 0u; }
    }
}

// -------- persistent wavefront LSTM: weights resident in smem --------
// static smem: As(2x32x72 h) + Cs(32x64 f) + cst(512 f) + par(112 f)
// dynamic smem: Bs = 64 rows x LB_LD halves = 197632 B (gate weights, resident)
#define LB_LD 1544
#define LSTM_DSMEM (64*LB_LD*2)

__global__ void __launch_bounds__(256) lstm_wave(
    const float* __restrict__ Wi, const float* __restrict__ Wf,
    const float* __restrict__ Wo, const float* __restrict__ Wg,
    const float* __restrict__ bi, const float* __restrict__ bf,
    const float* __restrict__ bo, const float* __restrict__ bg,
    const float* __restrict__ pci, const float* __restrict__ pcf,
    const float* __restrict__ pco)
{
    extern __shared__ __half Bs[];           // [64][LB_LD]
    __shared__ __half As[2][32*72];
    __shared__ float  Cs[32*64];
    __shared__ float  cst[512];
    __shared__ float  par[112];

    const int cta = blockIdx.x;
    const int j   = cta >> 5;
    const int n0  = (cta & 31) * 16;
    const int tid = threadIdx.x;
    const int warp = tid >> 5, lane = tid & 31;
    const int wm = warp & 1;
    const int wn = warp >> 1;

    const int Keff = (j == 0) ? 1024 : 1536;
    const int nk = Keff >> 6;

    if (tid < 16) {
        int idx = j * HID + n0 + tid;
        par[tid]    = bi[idx];  par[16+tid] = bf[idx];
        par[32+tid] = bo[idx];  par[48+tid] = bg[idx];
        par[64+tid] = pci[idx]; par[80+tid] = pcf[idx];
        par[96+tid] = pco[idx];
    }
    for (int i = tid; i < 512; i += 256) cst[i] = 0.f;

    // ---- one-time weight preload: fp32 global -> fp16 smem (k-compacted) ----
    for (int p = tid*4; p < 64*Keff; p += 1024) {
        int row = p / Keff, k = p - row*Keff;
        int kr = (j == 0 && k >= 512) ? k + 512 : k;
        int gate = row >> 4;
        int n = n0 + (row & 15);
        const float* wsel = (gate == 0) ? Wi : (gate == 1) ? Wf : (gate == 2) ? Wo : Wg;
        float4 v = *(const float4*)(wsel + (size_t)(j*HID + n)*VSZ + kr);
        __half2* d = (__half2*)(Bs + row*LB_LD + k);
        d[0] = __floats2half2_rn(v.x, v.y);
        d[1] = __floats2half2_rn(v.z, v.w);
    }
    __syncthreads();

    for (int w = 0; w < S_LEN + NLAYER - 1; ++w) {
        const int t = w - j;
        if (t >= 0 && t < S_LEN) {
            float acc[2][4] = {};
            float4 ra;

            auto loadA = [&](int kk) {
                int r = tid >> 3, c8 = tid & 7;
                int kc = kk + c8*8;
                int kr = (j == 0 && kc >= 512) ? kc + 512 : kc;
                const __half* src;
                if (kr < 512)
                    src = g_xh + (size_t)(t*BATCH + r)*NIN + kr;
                else if (kr < 1024)
                    src = g_Hch + (size_t)((t+1)*BATCH + r)*VSZ + (j-1)*HID + (kr-512);
                else
                    src = g_Hch + (size_t)(t*BATCH + r)*VSZ + j*HID + (kr-1024);
                ra = *(const float4*)src;
            };
            auto stsA = [&](int b) {
                int r = tid >> 3, c8 = tid & 7;
                *(float4*)(&As[b][r*72 + c8*8]) = ra;
            };

            loadA(0); stsA(0);
            for (int kt = 0; kt < nk; ++kt) {
                if (kt + 1 < nk) loadA((kt+1)*64);
                __syncthreads();
                const int buf = kt & 1;
#pragma unroll
                for (int ks = 0; ks < 4; ++ks) {
                    unsigned a0, a1, a2, a3, b0, b1, b2, b3;
                    unsigned aad = scvt(&As[buf][(wm*16 + (lane & 15))*72
                                                 + ks*16 + ((lane >> 4) << 3)]);
                    ldm4(a0, a1, a2, a3, aad);
                    unsigned bad = scvt(&Bs[(wn*16 + ((lane >> 4) << 3) + (lane & 7))*LB_LD
                                            + kt*64 + ks*16 + (((lane >> 3) & 1) << 3)]);
                    ldm4(b0, b1, b2, b3, bad);
                    mma16(acc[0], a0, a1, a2, a3, b0, b1);
                    mma16(acc[1], a0, a1, a2, a3, b2, b3);
                }
                if (kt + 1 < nk) stsA((kt + 1) & 1);
            }
#pragma unroll
            for (int nf = 0; nf < 2; ++nf) {
                int row = wm*16 + (lane >> 2);
                int col = wn*16 + nf*8 + (lane & 3)*2;
                Cs[row*64 + col]       = acc[nf][0];
                Cs[row*64 + col + 1]   = acc[nf][1];
                Cs[(row+8)*64 + col]   = acc[nf][2];
                Cs[(row+8)*64 + col+1] = acc[nf][3];
            }
            __syncthreads();
            for (int p = tid; p < 512; p += 256) {
                int b = p >> 4, hc = p & 15;
                float zi = Cs[b*64 + hc],      zf = Cs[b*64 + 16 + hc];
                float zo = Cs[b*64 + 32 + hc], zg = Cs[b*64 + 48 + hc];
                float c = cst[p];
                float it = sigm(zi + par[hc]    + par[64+hc]*c);
                float ft = sigm(zf + par[16+hc] + par[80+hc]*c);
                float ct = it * tanhf(zg + par[48+hc]) + ft * c;
                float ot = sigm(zo + par[32+hc] + par[96+hc]*c);  // peephole on OLD c
                float h  = ot * tanhf(ct);
                cst[p] = ct;
                g_Hch[(size_t)((t+1)*BATCH + b)*VSZ + j*HID + n0 + hc] = __float2half_rn(h);
            }
        }
        // ---- grid barrier (deadline-bounded spin: hang -> finite wrong answer) ----
        __threadfence();
        __syncthreads();
        if (tid == 0) {
            unsigned arr = atomicAdd(&g_arrive, 1u) + 1u;
            if (arr == (unsigned)((w + 1) * LSTM_NCTA)) {
                atomicExch(&g_epoch, (unsigned)(w + 1));
            } else {
                unsigned long long dl = clock64() + 2000000000ULL;
                volatile unsigned* ep = &g_epoch;
                while (*ep < (unsigned)(w + 1)) {
                    if (clock64() > dl) break;
                }
                __threadfence();
            }
        }
        __syncthreads();
    }
}

// -------- fp16 tensor GEMM: C[M,N] = A[M,K] @ W[N,K]^T + bias --------
// BM=128, BN=128, BK=64, 3-stage cp.async ring, 8 warps (2m x 4n),
// warp tile 64x32, 2 CTAs/SM.
#define GH_LD   72
#define GH_AB   (128*GH_LD*2)
#define GH_BB   (128*GH_LD*2)
#define GH_STG  (GH_AB + GH_BB)        // 36864 B
#define GH_SMEM (3*GH_STG)             // 110592 B

__global__ void __launch_bounds__(256, 2)
gemm_h(const __half* __restrict__ A, int lda,
       const __half* __restrict__ W, int ldw,
       const float* __restrict__ bias,
       float* __restrict__ Cf, __half* __restrict__ Ch, int out_half,
       int N, int K)
{
    extern __shared__ char smg[];
    const int tid = threadIdx.x;
    const int warp = tid >> 5, lane = tid & 31;
    const int wm = warp & 1, wn = warp >> 1;
    const int m0 = blockIdx.x * 128;
    const int n0 = blockIdx.y * 128;
    const int nk = K >> 6;

    auto fill = [&](int c, int s) {
        int k0 = c << 6;
        char* sA = smg + s*GH_STG;
        char* sB = sA + GH_AB;
#pragma unroll
        for (int q = 0; q < 4; ++q) {
            int id = tid + q*256, r = id >> 3, c16 = id & 7;
            cpa16(scvt(sA + (r*GH_LD + c16*8)*2),
                  A + (size_t)(m0 + r)*lda + k0 + c16*8, 16);
        }
#pragma unroll
        for (int q = 0; q < 4; ++q) {
            int id = tid + q*256, r = id >> 3, c16 = id & 7;
            int n = n0 + r;
            int ncl = (n < N) ? n : 0;
            int sz = (n < N) ? 16 : 0;
            cpa16(scvt(sB + (r*GH_LD + c16*8)*2),
                  W + (size_t)ncl*ldw + k0 + c16*8, sz);
        }
        cpa_commit();
    };

    float acc[4][4][4] = {};
    fill(0, 0); fill(1, 1);

    for (int c = 0; c < nk; ++c) {
        asm volatile("cp.async.wait_group 1;" ::: "memory");
        __syncthreads();
        if (c + 2 < nk) fill(c + 2, (c + 2) % 3);
        else cpa_commit();

        const char* sA = smg + (c % 3)*GH_STG;
        const char* sB = sA + GH_AB;
#pragma unroll
        for (int ks = 0; ks < 4; ++ks) {
            unsigned a[4][4], b[4][2];
#pragma unroll
            for (int mf = 0; mf < 4; ++mf) {
                unsigned ad = scvt(sA + ((wm*64 + mf*16 + (lane & 15))*GH_LD
                                         + ks*16 + ((lane >> 4) << 3))*2);
                ldm4(a[mf][0], a[mf][1], a[mf][2], a[mf][3], ad);
            }
#pragma unroll
            for (int np = 0; np < 2; ++np) {
                unsigned bd = scvt(sB + ((wn*32 + np*16 + ((lane >> 4) << 3) + (lane & 7))*GH_LD
                                         + ks*16 + (((lane >> 3) & 1) << 3))*2);
                ldm4(b[2*np][0], b[2*np][1], b[2*np+1][0], b[2*np+1][1], bd);
            }
#pragma unroll
            for (int nf = 0; nf < 4; ++nf)
#pragma unroll
                for (int mf = 0; mf < 4; ++mf)
                    mma16(acc[mf][nf], a[mf][0], a[mf][1], a[mf][2], a[mf][3],
                          b[nf][0], b[nf][1]);
        }
    }

#pragma unroll
    for (int mf = 0; mf < 4; ++mf) {
#pragma unroll
        for (int nf = 0; nf < 4; ++nf) {
            int r  = m0 + wm*64 + mf*16 + (lane >> 2);
            int cn = n0 + wn*32 + nf*8 + (lane & 3)*2;
#pragma unroll
            for (int h2 = 0; h2 < 2; ++h2) {
                int rr = r + h2*8;
                float v0 = acc[mf][nf][2*h2]     + ((cn < N) ? bias[cn] : 0.f);
                float v1 = acc[mf][nf][2*h2 + 1] + ((cn+1 < N) ? bias[cn+1] : 0.f);
                if (out_half) {
                    if (cn < N)     Ch[(size_t)rr*N + cn]     = __float2half_rn(v0);
                    if (cn + 1 < N) Ch[(size_t)rr*N + cn + 1] = __float2half_rn(v1);
                } else {
                    if (cn < N)     Cf[(size_t)rr*N + cn]     = v0;
                    if (cn + 1 < N) Cf[(size_t)rr*N + cn + 1] = v1;
                }
            }
        }
    }
}

extern "C" void kernel_launch(void* const* d_in, const int* in_sizes, int n_in,
                              void* d_out, int out_size) {
    const int*   ids  = (const int*)  d_in[0];
    const float* emb  = (const float*)d_in[1];
    const float* Wi   = (const float*)d_in[2];
    const float* bi   = (const float*)d_in[3];
    const float* Wf   = (const float*)d_in[4];
    const float* bf   = (const float*)d_in[5];
    const float* Wo   = (const float*)d_in[6];
    const float* bo   = (const float*)d_in[7];
    const float* Wg   = (const float*)d_in[8];
    const float* bg   = (const float*)d_in[9];
    const float* pci  = (const float*)d_in[10];
    const float* pcf  = (const float*)d_in[11];
    const float* pco  = (const float*)d_in[12];
    const float* Why  = (const float*)d_in[13];
    const float* bhy  = (const float*)d_in[14];
    const float* Wdec = (const float*)d_in[15];
    const float* bdec = (const float*)d_in[16];
    float* out = (float*)d_out;

    cudaFuncSetAttribute(gemm_h, cudaFuncAttributeMaxDynamicSharedMemorySize, GH_SMEM);
    cudaFuncSetAttribute(lstm_wave, cudaFuncAttributeMaxDynamicSharedMemorySize, LSTM_DSMEM);

    __half *whyh, *wdech, *hch, *yh;
    cudaGetSymbolAddress((void**)&whyh,  g_WhyH);
    cudaGetSymbolAddress((void**)&wdech, g_WdecH);
    cudaGetSymbolAddress((void**)&hch,   g_Hch);
    cudaGetSymbolAddress((void**)&yh,    g_yh);

    cvt_out<<<2048, 256>>>((const float4*)Why, (const float4*)Wdec);
    init_embed<<<MROWS + 16, 256>>>(ids, emb);
    lstm_wave<<<LSTM_NCTA, 256, LSTM_DSMEM>>>(Wi, Wf, Wo, Wg,
                                              bi, bf, bo, bg, pci, pcf, pco);

    {   // y = Hcat @ Why^T + bhy  (M=4096, N=512, K=1536) -> fp16 y
        dim3 grid(MROWS/128, (HID + 127)/128);
        gemm_h<<<grid, 256, GH_SMEM>>>(hch + (size_t)BATCH*VSZ, VSZ,
                                       whyh, VSZ, bhy, nullptr, yh, 1, HID, VSZ);
    }
    {   // logits = y @ Wdec^T + bdec  (M=4096, N=50257, K=512) -> fp32 out
        dim3 grid(MROWS/128, (NVOC + 127)/128);
        gemm_h<<<grid, 256, GH_SMEM>>>(yh, HID, wdech, HID, bdec,
                                       out, nullptr, 0, NVOC, HID);
    }
}